// round 1
// baseline (speedup 1.0000x reference)
#include <cuda_runtime.h>
#include <cuda_bf16.h>

#define C_CLASSES 5

__device__ float  g_pcnl[C_CLASSES];
__device__ double g_acc[2];   // [0]=num, [1]=den

// ---------------------------------------------------------------------------
// Kernel 1: build PCNL table from distribution, zero accumulators.
// ---------------------------------------------------------------------------
__global__ void owe_init_kernel(const float* __restrict__ dist) {
    if (threadIdx.x == 0 && blockIdx.x == 0) {
        float cs[C_CLASSES];
        float c = 0.f;
        #pragma unroll
        for (int i = 0; i < C_CLASSES; i++) { c += dist[i]; cs[i] = c; }
        float denom = 2.0f * cs[C_CLASSES - 1] - dist[0] - dist[C_CLASSES - 1];
        float inv = 1.0f / denom;
        #pragma unroll
        for (int i = 0; i < C_CLASSES; i++)
            g_pcnl[i] = (2.0f * cs[i] - dist[i] - dist[0]) * inv;
        g_acc[0] = 0.0;
        g_acc[1] = 0.0;
    }
}

// lookup(x): x is an integral float (floor or floor+1).
// in-range [0, C-1] -> pcnl[(int)x], else x / (C-1).
__device__ __forceinline__ float owe_lookup(float v, const float* __restrict__ pcnl) {
    if (v >= 0.0f && v <= (float)(C_CLASSES - 1)) {
        return pcnl[(int)v];
    }
    return v * (1.0f / (float)(C_CLASSES - 1));
}

__device__ __forceinline__ void owe_elem(float x, int t,
                                         const float* __restrict__ pcnl,
                                         const float* __restrict__ w,
                                         float& num, float& den) {
    float f  = floorf(x);
    float pf = owe_lookup(f, pcnl);
    float pc = owe_lookup(f + 1.0f, pcnl);
    float ip = pf + (pc - pf) * (x - f);
    float d  = ip - pcnl[t];
    float tw = w[t];
    num = fmaf(d * d, tw, num);
    den += tw;
}

// ---------------------------------------------------------------------------
// Kernel 2: main streaming reduction. float4/int4 vector loads, grid-stride.
// ---------------------------------------------------------------------------
__global__ void __launch_bounds__(256)
owe_main_kernel(const float4* __restrict__ inp4,
                const int4*  __restrict__ tgt4,
                const float* __restrict__ weight,
                int n4,
                const float* __restrict__ inp_tail,
                const int*   __restrict__ tgt_tail,
                int tail_start, int n_total) {
    __shared__ float s_pcnl[C_CLASSES];
    __shared__ float s_w[C_CLASSES];
    if (threadIdx.x < C_CLASSES) {
        s_pcnl[threadIdx.x] = g_pcnl[threadIdx.x];
        s_w[threadIdx.x]    = weight[threadIdx.x];
    }
    __syncthreads();

    float num = 0.0f, den = 0.0f;

    int tid    = blockIdx.x * blockDim.x + threadIdx.x;
    int stride = gridDim.x * blockDim.x;

    // Main vectorized loop: unroll by 2 for MLP (2x float4 + 2x int4 in flight)
    int i = tid;
    for (; i + stride < n4; i += 2 * stride) {
        float4 x0 = inp4[i];
        int4   t0 = tgt4[i];
        float4 x1 = inp4[i + stride];
        int4   t1 = tgt4[i + stride];
        owe_elem(x0.x, t0.x, s_pcnl, s_w, num, den);
        owe_elem(x0.y, t0.y, s_pcnl, s_w, num, den);
        owe_elem(x0.z, t0.z, s_pcnl, s_w, num, den);
        owe_elem(x0.w, t0.w, s_pcnl, s_w, num, den);
        owe_elem(x1.x, t1.x, s_pcnl, s_w, num, den);
        owe_elem(x1.y, t1.y, s_pcnl, s_w, num, den);
        owe_elem(x1.z, t1.z, s_pcnl, s_w, num, den);
        owe_elem(x1.w, t1.w, s_pcnl, s_w, num, den);
    }
    for (; i < n4; i += stride) {
        float4 x0 = inp4[i];
        int4   t0 = tgt4[i];
        owe_elem(x0.x, t0.x, s_pcnl, s_w, num, den);
        owe_elem(x0.y, t0.y, s_pcnl, s_w, num, den);
        owe_elem(x0.z, t0.z, s_pcnl, s_w, num, den);
        owe_elem(x0.w, t0.w, s_pcnl, s_w, num, den);
    }
    // Scalar tail (n_total not multiple of 4) — N=16.7M is divisible, but be safe.
    for (int j = tail_start + tid; j < n_total; j += stride) {
        owe_elem(inp_tail[j], tgt_tail[j], s_pcnl, s_w, num, den);
    }

    // Warp reduction
    #pragma unroll
    for (int off = 16; off > 0; off >>= 1) {
        num += __shfl_down_sync(0xFFFFFFFFu, num, off);
        den += __shfl_down_sync(0xFFFFFFFFu, den, off);
    }

    // Block reduction via shared memory
    __shared__ float s_num[8];
    __shared__ float s_den[8];
    int lane = threadIdx.x & 31;
    int warp = threadIdx.x >> 5;
    if (lane == 0) { s_num[warp] = num; s_den[warp] = den; }
    __syncthreads();
    if (warp == 0) {
        float bn = (lane < (blockDim.x >> 5)) ? s_num[lane] : 0.0f;
        float bd = (lane < (blockDim.x >> 5)) ? s_den[lane] : 0.0f;
        #pragma unroll
        for (int off = 4; off > 0; off >>= 1) {
            bn += __shfl_down_sync(0xFFFFFFFFu, bn, off);
            bd += __shfl_down_sync(0xFFFFFFFFu, bd, off);
        }
        if (lane == 0) {
            atomicAdd(&g_acc[0], (double)bn);
            atomicAdd(&g_acc[1], (double)bd);
        }
    }
}

// ---------------------------------------------------------------------------
// Kernel 3: finalize.
// ---------------------------------------------------------------------------
__global__ void owe_final_kernel(float* __restrict__ out) {
    if (threadIdx.x == 0 && blockIdx.x == 0) {
        out[0] = (float)(g_acc[0] / g_acc[1]);
    }
}

extern "C" void kernel_launch(void* const* d_in, const int* in_sizes, int n_in,
                              void* d_out, int out_size) {
    const float* inp  = (const float*)d_in[0];
    const int*   tgt  = (const int*)d_in[1];
    const float* wgt  = (const float*)d_in[2];
    const float* dist = (const float*)d_in[3];
    float* out = (float*)d_out;

    int n  = in_sizes[0];
    int n4 = n >> 2;           // float4 count
    int tail_start = n4 << 2;  // scalar tail start

    owe_init_kernel<<<1, 32>>>(dist);

    const int threads = 256;
    int blocks = 148 * 8;  // 1184 blocks, grid-stride
    int max_useful = (n4 + threads - 1) / threads;
    if (blocks > max_useful && max_useful > 0) blocks = max_useful;
    if (blocks < 1) blocks = 1;

    owe_main_kernel<<<blocks, threads>>>((const float4*)inp, (const int4*)tgt,
                                         wgt, n4, inp, tgt, tail_start, n);

    owe_final_kernel<<<1, 32>>>(out);
}

// round 2
// speedup vs baseline: 1.0685x; 1.0685x over previous
#include <cuda_runtime.h>
#include <cuda_bf16.h>

#define C_CLASSES 5

__device__ double g_acc[2];   // [0]=num, [1]=den. Zero-init at load; finalizer resets.

// lookup(x): x is an integral float (floor or floor+1).
// in-range [0, C-1] -> pcnl[(int)x], else x / (C-1).
__device__ __forceinline__ float owe_lookup(float v, const float* __restrict__ pcnl) {
    if (v >= 0.0f && v <= (float)(C_CLASSES - 1)) {
        return pcnl[(int)v];
    }
    return v * (1.0f / (float)(C_CLASSES - 1));
}

__device__ __forceinline__ void owe_elem(float x, int t,
                                         const float* __restrict__ pcnl,
                                         const float* __restrict__ w,
                                         float& num, float& den) {
    float f  = floorf(x);
    float pf = owe_lookup(f, pcnl);
    float pc = owe_lookup(f + 1.0f, pcnl);
    float ip = pf + (pc - pf) * (x - f);
    float d  = ip - pcnl[t];
    float tw = w[t];
    num = fmaf(d * d, tw, num);
    den += tw;
}

// ---------------------------------------------------------------------------
// Main streaming reduction. Each block recomputes the PCNL table inline
// (dist/weight are 5 floats, L2-resident after the first block touches them).
// ---------------------------------------------------------------------------
__global__ void __launch_bounds__(256)
owe_main_kernel(const float4* __restrict__ inp4,
                const int4*  __restrict__ tgt4,
                const float* __restrict__ weight,
                const float* __restrict__ dist,
                int n4,
                const float* __restrict__ inp_tail,
                const int*   __restrict__ tgt_tail,
                int tail_start, int n_total) {
    __shared__ float s_pcnl[C_CLASSES];
    __shared__ float s_w[C_CLASSES];
    if (threadIdx.x == 0) {
        float ds[C_CLASSES], cs[C_CLASSES];
        float c = 0.f;
        #pragma unroll
        for (int i = 0; i < C_CLASSES; i++) { ds[i] = dist[i]; c += ds[i]; cs[i] = c; }
        float inv = 1.0f / (2.0f * cs[C_CLASSES - 1] - ds[0] - ds[C_CLASSES - 1]);
        #pragma unroll
        for (int i = 0; i < C_CLASSES; i++)
            s_pcnl[i] = (2.0f * cs[i] - ds[i] - ds[0]) * inv;
    }
    if (threadIdx.x < C_CLASSES) {
        s_w[threadIdx.x] = weight[threadIdx.x];
    }
    __syncthreads();

    float num = 0.0f, den = 0.0f;

    int tid    = blockIdx.x * blockDim.x + threadIdx.x;
    int stride = gridDim.x * blockDim.x;

    // Main vectorized loop: unroll by 2 for MLP (2x float4 + 2x int4 in flight)
    int i = tid;
    for (; i + stride < n4; i += 2 * stride) {
        float4 x0 = inp4[i];
        int4   t0 = tgt4[i];
        float4 x1 = inp4[i + stride];
        int4   t1 = tgt4[i + stride];
        owe_elem(x0.x, t0.x, s_pcnl, s_w, num, den);
        owe_elem(x0.y, t0.y, s_pcnl, s_w, num, den);
        owe_elem(x0.z, t0.z, s_pcnl, s_w, num, den);
        owe_elem(x0.w, t0.w, s_pcnl, s_w, num, den);
        owe_elem(x1.x, t1.x, s_pcnl, s_w, num, den);
        owe_elem(x1.y, t1.y, s_pcnl, s_w, num, den);
        owe_elem(x1.z, t1.z, s_pcnl, s_w, num, den);
        owe_elem(x1.w, t1.w, s_pcnl, s_w, num, den);
    }
    for (; i < n4; i += stride) {
        float4 x0 = inp4[i];
        int4   t0 = tgt4[i];
        owe_elem(x0.x, t0.x, s_pcnl, s_w, num, den);
        owe_elem(x0.y, t0.y, s_pcnl, s_w, num, den);
        owe_elem(x0.z, t0.z, s_pcnl, s_w, num, den);
        owe_elem(x0.w, t0.w, s_pcnl, s_w, num, den);
    }
    // Scalar tail (n_total not multiple of 4)
    for (int j = tail_start + tid; j < n_total; j += stride) {
        owe_elem(inp_tail[j], tgt_tail[j], s_pcnl, s_w, num, den);
    }

    // Warp reduction
    #pragma unroll
    for (int off = 16; off > 0; off >>= 1) {
        num += __shfl_down_sync(0xFFFFFFFFu, num, off);
        den += __shfl_down_sync(0xFFFFFFFFu, den, off);
    }

    // Block reduction via shared memory
    __shared__ float s_num[8];
    __shared__ float s_den[8];
    int lane = threadIdx.x & 31;
    int warp = threadIdx.x >> 5;
    if (lane == 0) { s_num[warp] = num; s_den[warp] = den; }
    __syncthreads();
    if (warp == 0) {
        float bn = (lane < (blockDim.x >> 5)) ? s_num[lane] : 0.0f;
        float bd = (lane < (blockDim.x >> 5)) ? s_den[lane] : 0.0f;
        #pragma unroll
        for (int off = 4; off > 0; off >>= 1) {
            bn += __shfl_down_sync(0xFFFFFFFFu, bn, off);
            bd += __shfl_down_sync(0xFFFFFFFFu, bd, off);
        }
        if (lane == 0) {
            atomicAdd(&g_acc[0], (double)bn);
            atomicAdd(&g_acc[1], (double)bd);
        }
    }
}

// ---------------------------------------------------------------------------
// Finalize: write result, then reset accumulators so the next call
// (graph replay) starts from zero. Deterministic across calls.
// ---------------------------------------------------------------------------
__global__ void owe_final_kernel(float* __restrict__ out) {
    if (threadIdx.x == 0 && blockIdx.x == 0) {
        out[0] = (float)(g_acc[0] / g_acc[1]);
        g_acc[0] = 0.0;
        g_acc[1] = 0.0;
    }
}

extern "C" void kernel_launch(void* const* d_in, const int* in_sizes, int n_in,
                              void* d_out, int out_size) {
    const float* inp  = (const float*)d_in[0];
    const int*   tgt  = (const int*)d_in[1];
    const float* wgt  = (const float*)d_in[2];
    const float* dist = (const float*)d_in[3];
    float* out = (float*)d_out;

    int n  = in_sizes[0];
    int n4 = n >> 2;           // float4 count
    int tail_start = n4 << 2;  // scalar tail start

    const int threads = 256;
    int blocks = 148 * 8;  // 1184 blocks, grid-stride
    int max_useful = (n4 + threads - 1) / threads;
    if (blocks > max_useful && max_useful > 0) blocks = max_useful;
    if (blocks < 1) blocks = 1;

    owe_main_kernel<<<blocks, threads>>>((const float4*)inp, (const int4*)tgt,
                                         wgt, dist, n4, inp, tgt, tail_start, n);

    owe_final_kernel<<<1, 32>>>(out);
}

// round 3
// speedup vs baseline: 1.0696x; 1.0011x over previous
#include <cuda_runtime.h>
#include <cuda_bf16.h>

#define C_CLASSES 5
#define NREP 4            // shared-table replicas (8-word stride -> distinct bank octets)

__device__ double   g_acc[2];   // [0]=num, [1]=den. Zero-init at load; last block resets.
__device__ unsigned g_count;    // blocks-done counter. Zero-init; last block resets.

// ---------------------------------------------------------------------------
// Per-element core: j = floor(x)+1 indexes the extended table
//   ext[0] = -1/(C-1)           (fallback for floor = -1)
//   ext[1..C] = pcnl[0..C-1]
//   ext[C+1] = C/(C-1)          (fallback for floor+1 = C)
// ---------------------------------------------------------------------------
__device__ __forceinline__ void owe_elem(float x, int t,
                                         const float* __restrict__ ext,
                                         const float* __restrict__ tp,
                                         const float* __restrict__ tw,
                                         float& num, float& den) {
    float f  = floorf(x);
    int   j  = (int)f + 1;
    j = max(0, min(j, C_CLASSES));        // never active for the given input range
    float pf = ext[j];
    float pc = ext[j + 1];
    float ip = fmaf(pc - pf, x - f, pf);
    float d  = ip - tp[t];
    float w  = tw[t];
    num = fmaf(d * d, w, num);
    den += w;
}

// ---------------------------------------------------------------------------
// Single fused kernel: stream + reduce + (last block) finalize.
// ---------------------------------------------------------------------------
__global__ void __launch_bounds__(256)
owe_kernel(const float4* __restrict__ inp4,
           const int4*  __restrict__ tgt4,
           const float* __restrict__ weight,
           const float* __restrict__ dist,
           int n4,
           const float* __restrict__ inp_tail,
           const int*   __restrict__ tgt_tail,
           int tail_start, int n_total,
           float* __restrict__ out) {
    // Replicated tables: replica r occupies words [8r, 8r+8) -> banks 8r..8r+7.
    __shared__ float s_ext[NREP * 8];   // 7 entries used
    __shared__ float s_tp [NREP * 8];   // 5 entries used
    __shared__ float s_tw [NREP * 8];   // 5 entries used

    if (threadIdx.x == 0) {
        float ds[C_CLASSES], cs[C_CLASSES], pc[C_CLASSES], ww[C_CLASSES];
        float c = 0.f;
        #pragma unroll
        for (int i = 0; i < C_CLASSES; i++) { ds[i] = dist[i]; c += ds[i]; cs[i] = c; }
        float inv = 1.0f / (2.0f * cs[C_CLASSES - 1] - ds[0] - ds[C_CLASSES - 1]);
        #pragma unroll
        for (int i = 0; i < C_CLASSES; i++) {
            pc[i] = (2.0f * cs[i] - ds[i] - ds[0]) * inv;
            ww[i] = weight[i];
        }
        #pragma unroll
        for (int r = 0; r < NREP; r++) {
            s_ext[r * 8 + 0] = -1.0f / (float)(C_CLASSES - 1);
            #pragma unroll
            for (int i = 0; i < C_CLASSES; i++) {
                s_ext[r * 8 + 1 + i] = pc[i];
                s_tp [r * 8 + i]     = pc[i];
                s_tw [r * 8 + i]     = ww[i];
            }
            s_ext[r * 8 + C_CLASSES + 1] = (float)C_CLASSES / (float)(C_CLASSES - 1);
        }
    }
    __syncthreads();

    const int rep = (threadIdx.x & (NREP - 1)) * 8;
    const float* __restrict__ ext = s_ext + rep;
    const float* __restrict__ tp  = s_tp  + rep;
    const float* __restrict__ tw  = s_tw  + rep;

    float num = 0.0f, den = 0.0f;

    int tid    = blockIdx.x * blockDim.x + threadIdx.x;
    int stride = gridDim.x * blockDim.x;

    // Vectorized loop, unroll 2 (4 LDG.128 in flight per thread).
    int i = tid;
    for (; i + stride < n4; i += 2 * stride) {
        float4 x0 = inp4[i];
        int4   t0 = tgt4[i];
        float4 x1 = inp4[i + stride];
        int4   t1 = tgt4[i + stride];
        owe_elem(x0.x, t0.x, ext, tp, tw, num, den);
        owe_elem(x0.y, t0.y, ext, tp, tw, num, den);
        owe_elem(x0.z, t0.z, ext, tp, tw, num, den);
        owe_elem(x0.w, t0.w, ext, tp, tw, num, den);
        owe_elem(x1.x, t1.x, ext, tp, tw, num, den);
        owe_elem(x1.y, t1.y, ext, tp, tw, num, den);
        owe_elem(x1.z, t1.z, ext, tp, tw, num, den);
        owe_elem(x1.w, t1.w, ext, tp, tw, num, den);
    }
    for (; i < n4; i += stride) {
        float4 x0 = inp4[i];
        int4   t0 = tgt4[i];
        owe_elem(x0.x, t0.x, ext, tp, tw, num, den);
        owe_elem(x0.y, t0.y, ext, tp, tw, num, den);
        owe_elem(x0.z, t0.z, ext, tp, tw, num, den);
        owe_elem(x0.w, t0.w, ext, tp, tw, num, den);
    }
    for (int jj = tail_start + tid; jj < n_total; jj += stride) {
        owe_elem(inp_tail[jj], tgt_tail[jj], ext, tp, tw, num, den);
    }

    // Warp reduction
    #pragma unroll
    for (int off = 16; off > 0; off >>= 1) {
        num += __shfl_down_sync(0xFFFFFFFFu, num, off);
        den += __shfl_down_sync(0xFFFFFFFFu, den, off);
    }

    // Block reduction
    __shared__ float s_num[8];
    __shared__ float s_den[8];
    int lane = threadIdx.x & 31;
    int warp = threadIdx.x >> 5;
    if (lane == 0) { s_num[warp] = num; s_den[warp] = den; }
    __syncthreads();
    if (warp == 0) {
        float bn = (lane < (blockDim.x >> 5)) ? s_num[lane] : 0.0f;
        float bd = (lane < (blockDim.x >> 5)) ? s_den[lane] : 0.0f;
        #pragma unroll
        for (int off = 4; off > 0; off >>= 1) {
            bn += __shfl_down_sync(0xFFFFFFFFu, bn, off);
            bd += __shfl_down_sync(0xFFFFFFFFu, bd, off);
        }
        if (lane == 0) {
            atomicAdd(&g_acc[0], (double)bn);
            atomicAdd(&g_acc[1], (double)bd);
            __threadfence();
            unsigned done = atomicAdd(&g_count, 1u);
            if (done == gridDim.x - 1) {
                // Last block: read + reset accumulators atomically, finalize.
                double fn = __longlong_as_double(
                    atomicExch((unsigned long long*)&g_acc[0], 0ULL));
                double fd = __longlong_as_double(
                    atomicExch((unsigned long long*)&g_acc[1], 0ULL));
                out[0] = (float)(fn / fd);
                atomicExch(&g_count, 0u);
            }
        }
    }
}

extern "C" void kernel_launch(void* const* d_in, const int* in_sizes, int n_in,
                              void* d_out, int out_size) {
    const float* inp  = (const float*)d_in[0];
    const int*   tgt  = (const int*)d_in[1];
    const float* wgt  = (const float*)d_in[2];
    const float* dist = (const float*)d_in[3];
    float* out = (float*)d_out;

    int n  = in_sizes[0];
    int n4 = n >> 2;
    int tail_start = n4 << 2;

    const int threads = 256;
    int blocks = 148 * 8;  // 1184 blocks, grid-stride
    int max_useful = (n4 + threads - 1) / threads;
    if (blocks > max_useful && max_useful > 0) blocks = max_useful;
    if (blocks < 1) blocks = 1;

    owe_kernel<<<blocks, threads>>>((const float4*)inp, (const int4*)tgt,
                                    wgt, dist, n4, inp, tgt, tail_start, n, out);
}